// round 4
// baseline (speedup 1.0000x reference)
#include <cuda_runtime.h>
#include <cuda_bf16.h>
#include <math_constants.h>

// Problem constants
#define BATCH 16
#define SEQ   4096
#define EMB   2048
#define WIN   64

#define SLICES 8
#define STARTS_PER_SLICE (SEQ / SLICES)   // 512

// Scratch (static device arrays: allocation-free)
__device__ float        g_scores[BATCH * SEQ];
__device__ unsigned int g_bmax[BATCH];   // order-preserving-encoded per-batch max
__device__ unsigned int g_done;          // completion counter for kernel 2

// Order-preserving float <-> uint encoding (monotone for all non-NaN floats)
__device__ __forceinline__ unsigned int enc_f32(float f) {
    unsigned int u = __float_as_uint(f);
    return (u & 0x80000000u) ? ~u : (u | 0x80000000u);
}
__device__ __forceinline__ float dec_f32(unsigned int e) {
    unsigned int u = (e & 0x80000000u) ? (e ^ 0x80000000u) : ~e;
    return __uint_as_float(u);
}

// ---------------------------------------------------------------------------
// Kernel 1: s[b,t] = mask[b,t] ? dot(x[b,t,:], W) + bias : 0
// One warp per row. Streaming float4 loads (MLP=8), W in shared.
// Block 0 also resets the kernel-2 scratch (runs before kernel 2 by stream order).
// ---------------------------------------------------------------------------
__global__ __launch_bounds__(256) void score_kernel(
    const float* __restrict__ x,
    const int*   __restrict__ mask,   // bool mask coerced to int32 by harness
    const float* __restrict__ W,
    const float* __restrict__ bias)
{
    // Reset kernel-2 scratch each launch (graph replays included)
    if (blockIdx.x == 0 && threadIdx.x <= BATCH) {
        if (threadIdx.x < BATCH) g_bmax[threadIdx.x] = 0u;   // 0 < enc(any float)
        else                     g_done = 0u;
    }

    __shared__ float sW[EMB];
    for (int i = threadIdx.x; i < EMB; i += blockDim.x)
        sW[i] = W[i];
    __syncthreads();

    const int warpsPerBlock = blockDim.x >> 5;
    const int warp = blockIdx.x * warpsPerBlock + (threadIdx.x >> 5);
    const int lane = threadIdx.x & 31;
    if (warp >= BATCH * SEQ) return;

    // Prefetch mask early (lane 0 only needs it)
    int m = (lane == 0) ? mask[warp] : 0;

    const float4* __restrict__ xr = reinterpret_cast<const float4*>(x + (size_t)warp * EMB);
    const float4* __restrict__ wr = reinterpret_cast<const float4*>(sW);

    float acc = 0.0f;
    // EMB/4 = 512 float4 per row; 32 lanes -> 16 float4 per lane.
    // Two half-passes of 8 front-batched streaming LDG.128 each (MLP=8).
    #pragma unroll
    for (int h = 0; h < 2; h++) {
        float4 a[8];
        #pragma unroll
        for (int j = 0; j < 8; j++)
            a[j] = __ldcs(&xr[lane + (h * 8 + j) * 32]);
        #pragma unroll
        for (int j = 0; j < 8; j++) {
            float4 w = wr[lane + (h * 8 + j) * 32];
            acc = fmaf(a[j].x, w.x, acc);
            acc = fmaf(a[j].y, w.y, acc);
            acc = fmaf(a[j].z, w.z, acc);
            acc = fmaf(a[j].w, w.w, acc);
        }
    }

    // warp reduce
    #pragma unroll
    for (int o = 16; o > 0; o >>= 1)
        acc += __shfl_xor_sync(0xffffffffu, acc, o);

    if (lane == 0) {
        float v = (m != 0) ? (acc + bias[0]) : 0.0f;
        g_scores[warp] = v;
    }
}

// ---------------------------------------------------------------------------
// Kernel 2: 16 batches x 8 slices = 128 blocks, 128 threads each.
// Each thread: 4 consecutive window starts via rolling sum over smem stage.
// Per-batch max via atomicMax on encoded uint; last block writes out[].
// ---------------------------------------------------------------------------
__global__ __launch_bounds__(128) void window_max_kernel(float* __restrict__ out)
{
    __shared__ float s[STARTS_PER_SLICE + WIN];   // 576 floats
    __shared__ float red[4];
    __shared__ unsigned int isLast;

    const int tid = threadIdx.x;
    const int b   = blockIdx.x / SLICES;
    const int sl  = blockIdx.x % SLICES;
    const int base = sl * STARTS_PER_SLICE;

    // Stage this slice's scores (+ window tail) into shared
    for (int i = tid; i < STARTS_PER_SLICE + WIN; i += 128) {
        int g = base + i;
        s[i] = (g < SEQ) ? g_scores[b * SEQ + g] : 0.0f;
    }
    __syncthreads();

    // Thread t covers starts base+4t .. base+4t+3
    const int start0 = base + tid * 4;
    float best = -CUDART_INF_F;
    if (start0 <= SEQ - WIN) {
        // Initial 64-wide sum via 16 aligned float4 shared loads
        const float4* sv = reinterpret_cast<const float4*>(s) + tid;
        float sum = 0.0f;
        #pragma unroll
        for (int k = 0; k < WIN / 4; k++) {
            float4 v = sv[k];
            sum += (v.x + v.y) + (v.z + v.w);
        }
        best = sum;
        #pragma unroll
        for (int j = 1; j < 4; j++) {
            int i = start0 + j;
            if (i <= SEQ - WIN) {
                int li = tid * 4 + j;
                sum += s[li + WIN - 1] - s[li - 1];
                best = fmaxf(best, sum);
            }
        }
    }

    // Warp max reduce, then 4 warps -> thread 0
    #pragma unroll
    for (int o = 16; o > 0; o >>= 1)
        best = fmaxf(best, __shfl_xor_sync(0xffffffffu, best, o));
    if ((tid & 31) == 0) red[tid >> 5] = best;
    __syncthreads();

    if (tid == 0) {
        float m = fmaxf(fmaxf(red[0], red[1]), fmaxf(red[2], red[3]));
        atomicMax(&g_bmax[b], enc_f32(m));
        __threadfence();
        isLast = (atomicAdd(&g_done, 1u) == (unsigned)(gridDim.x - 1));
    }
    __syncthreads();

    // Last block to finish writes all outputs
    if (isLast && tid < BATCH) {
        unsigned int e = atomicAdd(&g_bmax[tid], 0u);  // ordered read
        out[tid] = dec_f32(e) * (1.0f / (float)WIN);
    }
}

// ---------------------------------------------------------------------------
// Launch
// ---------------------------------------------------------------------------
extern "C" void kernel_launch(void* const* d_in, const int* in_sizes, int n_in,
                              void* d_out, int out_size)
{
    const float* x    = (const float*)d_in[0];
    const int*   mask = (const int*)d_in[1];
    const float* W    = (const float*)d_in[2];
    const float* bias = (const float*)d_in[3];
    float*       out  = (float*)d_out;

    // Kernel 1: one warp per row, 8 warps per 256-thread block
    const int totalRows = BATCH * SEQ;               // 65536
    const int warpsPerBlock = 256 / 32;              // 8
    const int grid1 = (totalRows + warpsPerBlock - 1) / warpsPerBlock; // 8192
    score_kernel<<<grid1, 256>>>(x, mask, W, bias);

    // Kernel 2: 128 blocks (16 batches x 8 slices)
    window_max_kernel<<<BATCH * SLICES, 128>>>(out);
}